// round 15
// baseline (speedup 1.0000x reference)
#include <cuda_runtime.h>
#include <cuda_bf16.h>
#include <cuda_fp16.h>
#include <math.h>
#include <stdint.h>

#define B_  2
#define L_  8192
#define D_  64
#define CR_ 2048
#define NC_ 48
#define TE_ 512
#define NL_ 8
#define M_  1024
#define NCOL_ (B_*L_)
#define NBLK 256
#define NGRP 16
#define GRPSZ (NBLK/NGRP)

// ---------------- scratch ----------------
__device__ __half g_Wp[(size_t)M_*CR_];
__device__ __half g_Xp[(size_t)NCOL_*CR_];
__device__ __half g_QKCh[(size_t)M_*NCOL_];
__device__ __half g_AW[NL_*8*64*64];     // [i][slot][m][k]; slots: taps{0,1,3,4,2},q,k,v
__device__ __half g_fh[B_*D_*L_];
__device__ float g_f1T [NL_*64*64];
__device__ float g_f2T [NL_*64*64];
__device__ float g_fra [B_*D_*L_];
__device__ __half g_xq  [B_*D_*L_];
__device__ __half g_xk  [B_*D_*L_];
__device__ __half g_xv  [B_*D_*L_];
__device__ __half g_out1[B_*D_*L_];
__device__ float g_y   [B_*D_*L_];
__device__ float g_part[B_*D_*128*2];
__device__ float g_tproj[B_*D_];
__device__ float g_t1[B_*TE_];
__device__ float g_t2[B_*TE_];
__device__ unsigned g_bgrp[NGRP];
__device__ unsigned g_barc = 0;
__device__ unsigned g_barg = 0;
__device__ unsigned g_qdone[NL_];   // cumulative GEMM-slice completion counters
__device__ unsigned g_epoch = 0;    // bumped once per invocation (by pack_wp b0t0)

__device__ __forceinline__ uint32_t smem_u32(const void* p) {
    return (uint32_t)__cvta_generic_to_shared(p);
}
__device__ __forceinline__ void ldsm_x4(uint32_t* r, uint32_t addr) {
    asm volatile("ldmatrix.sync.aligned.m8n8.x4.shared.b16 {%0,%1,%2,%3}, [%4];"
                 : "=r"(r[0]), "=r"(r[1]), "=r"(r[2]), "=r"(r[3]) : "r"(addr));
}
__device__ __forceinline__ void ldsm_x4t(uint32_t* r, uint32_t addr) {
    asm volatile("ldmatrix.sync.aligned.m8n8.x4.trans.shared.b16 {%0,%1,%2,%3}, [%4];"
                 : "=r"(r[0]), "=r"(r[1]), "=r"(r[2]), "=r"(r[3]) : "r"(addr));
}
__device__ __forceinline__ void mma_fp16(float c[4], uint32_t a0, uint32_t a1, uint32_t a2,
                                         uint32_t a3, uint32_t b0, uint32_t b1) {
    asm volatile("mma.sync.aligned.m16n8k16.row.col.f32.f16.f16.f32 "
                 "{%0,%1,%2,%3}, {%4,%5,%6,%7}, {%8,%9}, {%0,%1,%2,%3};"
                 : "+f"(c[0]), "+f"(c[1]), "+f"(c[2]), "+f"(c[3])
                 : "r"(a0), "r"(a1), "r"(a2), "r"(a3), "r"(b0), "r"(b1));
}
__device__ __forceinline__ void cp16(uint32_t saddr, const void* gptr) {
    asm volatile("cp.async.cg.shared.global [%0], [%1], 16;" :: "r"(saddr), "l"(gptr));
}
#define CP_COMMIT() asm volatile("cp.async.commit_group;")
#define CP_WAIT1() asm volatile("cp.async.wait_group 1;")
#define CP_WAIT0() asm volatile("cp.async.wait_group 0;")

// two-level grid barrier with cumulative counters
__device__ __forceinline__ void gbar() {
    __syncthreads();
    if (threadIdx.x == 0) {
        __threadfence();
        const unsigned gen = *((volatile unsigned*)&g_barg);
        const int grp = blockIdx.x & (NGRP - 1);
        if (atomicAdd(&g_bgrp[grp], 1u) == (gen + 1) * GRPSZ - 1) {
            if (atomicAdd(&g_barc, 1u) == (gen + 1) * NGRP - 1) {
                __threadfence();
                atomicAdd(&g_barg, 1u);
            }
        }
        while (*((volatile unsigned*)&g_barg) == gen) { }
        __threadfence();
    }
    __syncthreads();
}

// ================== fp16 HMMA cross GEMM (sliced by layer via mbase) ==================
#define GM_BM 128
#define GM_BN 128
#define GM_BK 32
#define GM_NT (CR_/GM_BK)
#define APAD 40
#define GM_ST 3
#define GM_TILE (128*APAD)
#define GM_SMEM (GM_ST*2*GM_TILE*2)

__global__ void __launch_bounds__(256, 2) gemm_fp16_kernel(int mbase) {
    extern __shared__ __half gsm[];
    __half* As = gsm;
    __half* Bs = gsm + GM_ST*GM_TILE;
    const int tid = threadIdx.x, lane = tid & 31, wid = tid >> 5;
    const int wm = wid >> 2, wn = wid & 3;
    const int m0 = (mbase + blockIdx.x) * GM_BM;
    const int col0 = blockIdx.y * GM_BN;
    const int ldr = tid >> 1, ldc = (tid & 1) * 2;

    float acc[4][4][4];
#pragma unroll
    for (int i = 0; i < 4; ++i)
#pragma unroll
        for (int j = 0; j < 4; ++j)
#pragma unroll
            for (int q = 0; q < 4; ++q) acc[i][j][q] = 0.f;

    const int lrow = lane & 15, lhalf = lane >> 4;

    auto load_tile = [&](int kt, int buf) {
        const size_t gk = (size_t)kt * GM_BK;
        __half* ab = As + buf * GM_TILE;
        __half* bb = Bs + buf * GM_TILE;
#pragma unroll
        for (int s = 0; s < 2; ++s) {
            int c = ldc + s;
            cp16(smem_u32(ab + ldr * APAD + c * 8),
                 g_Wp + (size_t)(m0 + ldr) * CR_ + gk + c * 8);
            cp16(smem_u32(bb + ldr * APAD + c * 8),
                 g_Xp + (size_t)(col0 + ldr) * CR_ + gk + c * 8);
        }
        CP_COMMIT();
    };

    load_tile(0, 0);
    load_tile(1, 1);
    for (int kt = 0; kt < GM_NT; ++kt) {
        const int cur = kt % GM_ST;
        CP_WAIT1();
        __syncthreads();
        if (kt + 2 < GM_NT) load_tile(kt + 2, (kt + 2) % GM_ST);
        const __half* ab = As + cur * GM_TILE;
        const __half* bb = Bs + cur * GM_TILE;
#pragma unroll
        for (int kk2 = 0; kk2 < 2; ++kk2) {
            uint32_t a[4][4];
#pragma unroll
            for (int mt = 0; mt < 4; ++mt)
                ldsm_x4(a[mt], smem_u32(ab + (wm*64 + mt*16 + lrow) * APAD + kk2*16 + lhalf*8));
            uint32_t b[4][2];
#pragma unroll
            for (int nb2 = 0; nb2 < 2; ++nb2) {
                uint32_t r[4];
                ldsm_x4(r, smem_u32(bb + (wn*32 + nb2*16 + lrow) * APAD + kk2*16 + lhalf*8));
                b[nb2*2 + 0][0] = r[0]; b[nb2*2 + 0][1] = r[2];
                b[nb2*2 + 1][0] = r[1]; b[nb2*2 + 1][1] = r[3];
            }
#pragma unroll
            for (int mt = 0; mt < 4; ++mt)
#pragma unroll
                for (int nt = 0; nt < 4; ++nt)
                    mma_fp16(acc[mt][nt], a[mt][0], a[mt][1], a[mt][2], a[mt][3],
                             b[nt][0], b[nt][1]);
        }
    }
    const int grp = lane >> 2, qd = (lane & 3) * 2;
#pragma unroll
    for (int mt = 0; mt < 4; ++mt)
#pragma unroll
        for (int nt = 0; nt < 4; ++nt) {
            int m = m0 + wm*64 + mt*16 + grp;
            int n = col0 + wn*32 + nt*8 + qd;
            *(__half2*)(g_QKCh + (size_t)m * NCOL_ + n)       = __floats2half2_rn(acc[mt][nt][0], acc[mt][nt][1]);
            *(__half2*)(g_QKCh + (size_t)(m + 8) * NCOL_ + n) = __floats2half2_rn(acc[mt][nt][2], acc[mt][nt][3]);
        }
    // completion signal for this layer slice
    __threadfence();
    __syncthreads();
    if (tid == 0) atomicAdd(&g_qdone[m0 >> 7], 1u);
}

// ---------------- packing ----------------
__global__ void pack_wp_kernel(const float* __restrict__ qw, const float* __restrict__ kw) {
    if (blockIdx.x == 0 && threadIdx.x == 0) atomicAdd(&g_epoch, 1u);
    int idx = blockIdx.x * 256 + threadIdx.x;
    int m = idx >> 11, c = idx & 2047;
    int i = m >> 7, r = m & 127, s = r >> 6, d = r & 63;
    const float* src = s ? kw : qw;
    g_Wp[(size_t)m * CR_ + c] = __float2half(src[(i*64 + d)*2112 + 64 + c]);
}

__global__ void __launch_bounds__(256) xt_kernel(const float* __restrict__ x) {
    __shared__ float ts[32][33];
    const int lb = blockIdx.x * 32, kb = blockIdx.y * 32, n = blockIdx.z;
    const int tx = threadIdx.x & 31, ty = threadIdx.x >> 5;
#pragma unroll
    for (int r = ty; r < 32; r += 8)
        ts[r][tx] = x[((size_t)n * CR_ + kb + r) * L_ + lb + tx];
    __syncthreads();
#pragma unroll
    for (int r = ty; r < 32; r += 8)
        g_Xp[(size_t)(n * L_ + lb + r) * CR_ + kb + tx] = __float2half(ts[tx][r]);
}

__global__ void pack_aw_kernel(const float* __restrict__ convw, const float* __restrict__ qw,
                               const float* __restrict__ kw,   const float* __restrict__ vw,
                               const float* __restrict__ f1w,  const float* __restrict__ f2w) {
    int idx = blockIdx.x * 256 + threadIdx.x;
    if (idx < NL_*8*64*64) {
        int c = idx & 63, m = (idx >> 6) & 63, s = (idx >> 12) & 7, i = idx >> 15;
        const int tapmap[5] = {0, 1, 3, 4, 2};
        float v;
        if (s < 5)      v = convw[((i*64 + m)*64 + c)*5 + tapmap[s]];
        else if (s == 5) v = qw[(i*64 + m)*2112 + c];
        else if (s == 6) v = kw[(i*64 + m)*2112 + c];
        else             v = vw[(i*64 + m)*64 + c];
        g_AW[(size_t)(i*8 + s) * 4096 + m*64 + c] = __float2half(v);
    }
    if (idx < NL_*64*64) {
        int d = idx & 63, c = (idx >> 6) & 63, i = idx >> 12;
        g_f1T[idx] = f1w[(i*64 + d)*64 + c];
        g_f2T[idx] = f2w[(i*64 + d)*64 + c];
    }
}

// ---------------- timestep embedding ----------------
__global__ void temb1_kernel(const int* __restrict__ t, const float* __restrict__ w1,
                             const float* __restrict__ b1) {
    __shared__ float se[TE_];
    const int n = blockIdx.y, tid = threadIdx.x;
    const float tv = (float)t[n];
    if (tid < 256) {
        float f = expf((float)tid * (-logf(10000.0f) / 255.0f));
        se[tid] = sinf(tv * f);
        se[tid + 256] = cosf(tv * f);
    }
    __syncthreads();
    const int w = tid >> 5, lane = tid & 31;
    const int o = blockIdx.x * 8 + w;
    const float* wr = w1 + (size_t)o * TE_;
    float s = 0.f;
    for (int c = lane; c < TE_; c += 32) s += se[c] * wr[c];
#pragma unroll
    for (int off = 16; off; off >>= 1) s += __shfl_xor_sync(0xffffffffu, s, off);
    if (!lane) { s += b1[o]; g_t1[n*TE_ + o] = s / (1.f + expf(-s)); }
}
__global__ void temb2_kernel(const float* __restrict__ w2, const float* __restrict__ b2) {
    __shared__ float se[TE_];
    const int n = blockIdx.y, tid = threadIdx.x;
    se[tid] = g_t1[n*TE_ + tid];
    se[tid + 256] = g_t1[n*TE_ + tid + 256];
    __syncthreads();
    const int w = tid >> 5, lane = tid & 31;
    const int o = blockIdx.x * 8 + w;
    const float* wr = w2 + (size_t)o * TE_;
    float s = 0.f;
    for (int c = lane; c < TE_; c += 32) s += se[c] * wr[c];
#pragma unroll
    for (int off = 16; off; off >>= 1) s += __shfl_xor_sync(0xffffffffu, s, off);
    if (!lane) g_t2[n*TE_ + o] = s + b2[o];
}
__global__ void tembp_kernel(const float* __restrict__ wp, const float* __restrict__ bp) {
    __shared__ float se[TE_];
    const int n = blockIdx.y, tid = threadIdx.x;
    {
        float v0 = g_t2[n*TE_ + tid], v1 = g_t2[n*TE_ + tid + 256];
        se[tid]       = v0 / (1.f + expf(-v0));
        se[tid + 256] = v1 / (1.f + expf(-v1));
    }
    __syncthreads();
    const int w = tid >> 5, lane = tid & 31;
    const int o = blockIdx.x * 8 + w;
    const float* wr = wp + (size_t)o * TE_;
    float s = 0.f;
    for (int c = lane; c < TE_; c += 32) s += se[c] * wr[c];
#pragma unroll
    for (int off = 16; off; off >>= 1) s += __shfl_xor_sync(0xffffffffu, s, off);
    if (!lane) g_tproj[n*D_ + o] = s + bp[o];
}

// ---------------- conv_in ----------------
__global__ void __launch_bounds__(256) conv_in_kernel(const float* __restrict__ event,
                                                      const float* __restrict__ w,
                                                      const float* __restrict__ b) {
    __shared__ float Et[NC_][64];
    __shared__ float Wt[NC_][64];
    const int n = blockIdx.y, l0 = blockIdx.x * 64;
    const int tid = threadIdx.x, ty4 = (tid >> 4) << 2, tx4 = (tid & 15) << 2;
    for (int e = tid; e < NC_*64; e += 256) {
        int c = e >> 6, tt = e & 63;
        Et[c][tt] = event[(n*NC_ + c)*L_ + l0 + tt];
        Wt[c][tt] = w[tt*NC_ + c];
    }
    __syncthreads();
    float acc[4][4] = {};
#pragma unroll
    for (int c = 0; c < NC_; ++c) {
        const float4 a = *(const float4*)(&Wt[c][ty4]);
        const float4 x4 = *(const float4*)(&Et[c][tx4]);
        acc[0][0]+=a.x*x4.x; acc[0][1]+=a.x*x4.y; acc[0][2]+=a.x*x4.z; acc[0][3]+=a.x*x4.w;
        acc[1][0]+=a.y*x4.x; acc[1][1]+=a.y*x4.y; acc[1][2]+=a.y*x4.z; acc[1][3]+=a.y*x4.w;
        acc[2][0]+=a.z*x4.x; acc[2][1]+=a.z*x4.y; acc[2][2]+=a.z*x4.z; acc[2][3]+=a.z*x4.w;
        acc[3][0]+=a.w*x4.x; acc[3][1]+=a.w*x4.y; acc[3][2]+=a.w*x4.z; acc[3][3]+=a.w*x4.w;
    }
#pragma unroll
    for (int i = 0; i < 4; ++i)
#pragma unroll
        for (int j = 0; j < 4; ++j) {
            int d = ty4 + i, l = l0 + tx4 + j;
            size_t o = (size_t)(n*D_ + d)*L_ + l;
            float v = acc[i][j] + b[d] + g_tproj[n*D_ + d];
            g_fra[o] = v;
            g_fh[o] = __float2half(v);
        }
}

// ================== persistent layers kernel (88KB, 2/SM) ==================
#define LA_SMEM (40960 + 49152)

__device__ __forceinline__ void mm64(float acc[2][4][4], uint32_t Ah,
                                     uint32_t Bh, int wm, int wn, int lane) {
    const int lrow = lane & 15, lhalf = lane >> 4;
    const int bk = (lane & 7) + (((lane >> 3) & 1) << 3);
    const int bn8 = (lane >> 4) << 3;
#pragma unroll
    for (int k0 = 0; k0 < 4; ++k0) {
        uint32_t a[2][4];
#pragma unroll
        for (int mt = 0; mt < 2; ++mt) {
            int m = wm*32 + mt*16 + lrow;
            int ch = (k0*2 + lhalf) ^ (m & 7);
            ldsm_x4(a[mt], Ah + m*128 + ch*16);
        }
        uint32_t b[4][2];
#pragma unroll
        for (int ng = 0; ng < 2; ++ng) {
            int k = k0*16 + bk;
            int n = wn*32 + ng*16 + bn8;
            int ch = (n >> 3) ^ (k & 7);
            uint32_t r[4];
            ldsm_x4t(r, Bh + k*256 + ch*16);
            b[ng*2 + 0][0] = r[0]; b[ng*2 + 0][1] = r[1];
            b[ng*2 + 1][0] = r[2]; b[ng*2 + 1][1] = r[3];
        }
#pragma unroll
        for (int mt = 0; mt < 2; ++mt)
#pragma unroll
            for (int nt = 0; nt < 4; ++nt)
                mma_fp16(acc[mt][nt], a[mt][0], a[mt][1], a[mt][2], a[mt][3],
                         b[nt][0], b[nt][1]);
    }
}

__device__ void phaseA(char* dsm, int bidx, int layer, int dil, unsigned ep,
                       const float* convb, const float* qb,
                       const float* kb, const float* vb) {
    char* smA = dsm;             // 5 x 8KB
    char* smB = dsm + 40960;     // 3 x 16KB
    const int tid = threadIdx.x, lane = tid & 31, wid = tid >> 5;
    const int wm = wid >> 2, wn = wid & 3;
    const int l0 = (bidx & 63) * 128;
    const int nb = (bidx >> 6) & 1;
    const int z  = bidx >> 7;
    const __half* fh = g_fh + (size_t)nb * D_ * L_;
    const float* fb = g_fra + (size_t)nb * D_ * L_;

    auto loadA = [&](int slot, int buf) {
        const __half* src = g_AW + (size_t)(layer*8 + slot) * 4096;
        char* dh = smA + buf * 8192;
#pragma unroll
        for (int e = tid; e < 512; e += 256) {
            int m = e >> 3, c = e & 7;
            int off = m*128 + ((c ^ (m & 7)) << 4);
            cp16(smem_u32(dh + off), src + m*64 + c*8);
        }
    };
    auto loadB = [&](int shift, int buf) {
        char* dh = smB + buf * 16384;
        if ((shift & 7) == 0) {
#pragma unroll
            for (int e = tid; e < 1024; e += 256) {
                int k = e >> 4, c = e & 15;
                int gl = l0 + c*8 + shift;
                int off = k*256 + ((c ^ (k & 7)) << 4);
                if (gl >= 0 && gl + 8 <= L_) {
                    cp16(smem_u32(dh + off), fh + (size_t)k * L_ + gl);
                } else {
                    __half* ph = (__half*)(dh + off);
#pragma unroll
                    for (int u = 0; u < 8; ++u) {
                        int l = gl + u;
                        ph[u] = ((unsigned)l < (unsigned)L_) ? fh[(size_t)k * L_ + l] : __half(0.f);
                    }
                }
            }
        } else {
#pragma unroll
            for (int e = tid; e < 1024; e += 256) {
                int k = e >> 4, c = e & 15;
                int gl = l0 + c*8 + shift;
                int off = k*256 + ((c ^ (k & 7)) << 4);
                const float* src = fb + (size_t)k * L_;
                __half hb[8];
#pragma unroll
                for (int u = 0; u < 8; ++u) {
                    int l = gl + u;
                    hb[u] = __float2half(((unsigned)l < (unsigned)L_) ? __ldg(src + l) : 0.f);
                }
                *(uint4*)(dh + off) = *(uint4*)hb;
            }
        }
    };

    float acc[2][4][4];
#pragma unroll
    for (int i = 0; i < 2; ++i)
#pragma unroll
        for (int j = 0; j < 4; ++j)
#pragma unroll
            for (int q = 0; q < 4; ++q) acc[i][j][q] = 0.f;

    const int grp = lane >> 2, qd = (lane & 3) * 2;
    auto epilogue = [&](__half* dst, const float* bias, const __half* qkc) {
#pragma unroll
        for (int mt = 0; mt < 2; ++mt)
#pragma unroll
            for (int nt = 0; nt < 4; ++nt) {
                int m = wm*32 + mt*16 + grp;
                int n = wn*32 + nt*8 + qd;
                float v0 = acc[mt][nt][0] + bias[m];
                float v1 = acc[mt][nt][1] + bias[m];
                float v2 = acc[mt][nt][2] + bias[m + 8];
                float v3 = acc[mt][nt][3] + bias[m + 8];
                if (qkc) {
                    __half2 e0 = *(const __half2*)(qkc + (size_t)m * NCOL_ + n);
                    __half2 e1 = *(const __half2*)(qkc + (size_t)(m + 8) * NCOL_ + n);
                    v0 += __low2float(e0); v1 += __high2float(e0);
                    v2 += __low2float(e1); v3 += __high2float(e1);
                }
                *(__half2*)(dst + (size_t)(nb*D_ + m) * L_ + l0 + n)     = __floats2half2_rn(v0, v1);
                *(__half2*)(dst + (size_t)(nb*D_ + m + 8) * L_ + l0 + n) = __floats2half2_rn(v2, v3);
                acc[mt][nt][0] = acc[mt][nt][1] = acc[mt][nt][2] = acc[mt][nt][3] = 0.f;
            }
    };

    if (z == 0) {
        const int tapshift[5] = {-2*dil, -dil, dil, 2*dil, 0};
#pragma unroll
        for (int s = 0; s < 5; ++s) loadA(s, s);
        CP_COMMIT();
        loadB(tapshift[0], 0); CP_COMMIT();
        loadB(tapshift[1], 1); CP_COMMIT();
        for (int it = 0; it < 5; ++it) {
            if (it < 4) CP_WAIT1();
            else CP_WAIT0();
            __syncthreads();
            if (it + 2 < 5) { loadB(tapshift[it + 2], (it + 2) % 3); CP_COMMIT(); }
            mm64(acc, smem_u32(smA + it * 8192), smem_u32(smB + (it % 3) * 16384),
                 wm, wn, lane);
        }
        epilogue(g_out1, convb + layer*64, nullptr);
    } else {
        // wait for this layer's GEMM slice (produced on the forked stream)
        if (tid == 0) {
            const unsigned target = ep * 128u;
            while (*((volatile unsigned*)&g_qdone[layer]) < target) { }
            __threadfence();
        }
        loadB(0, 0);
        loadA(5, 0); loadA(6, 1); loadA(7, 2);
        CP_COMMIT();
        CP_WAIT0();
        __syncthreads();     // also publishes the qdone wait to all threads
        const uint32_t Bh = smem_u32(smB);
        mm64(acc, smem_u32(smA), Bh, wm, wn, lane);
        epilogue(g_xq, qb + layer*64, g_QKCh + (size_t)(layer*2)*64*NCOL_ + nb*L_ + l0);
        mm64(acc, smem_u32(smA + 8192), Bh, wm, wn, lane);
        epilogue(g_xk, kb + layer*64, g_QKCh + (size_t)(layer*2 + 1)*64*NCOL_ + nb*L_ + l0);
        mm64(acc, smem_u32(smA + 16384), Bh, wm, wn, lane);
        epilogue(g_xv, vb + layer*64, nullptr);
    }
}

// ---------------- phaseB ----------------
__device__ void phaseB(char* dsm, int bidx, int dil) {
    float (*satt)[64] = (float(*)[64])dsm;
    const int n = bidx >> 7, lblk = bidx & 127, l0 = lblk * 64;
    const int tid = threadIdx.x;
    {
        const int g = tid & 3, l = tid >> 2;
        const int lg = l0 + l;
        const __half* qp = g_xq + (size_t)n * D_ * L_ + lg;
        const __half* kp = g_xk + (size_t)n * D_ * L_;
        bool v[5]; int pc[5];
#pragma unroll
        for (int j = 0; j < 5; ++j) {
            int p = lg + (j - 2) * dil;
            v[j] = ((unsigned)p < (unsigned)L_);
            pc[j] = v[j] ? p : lg;
        }
        float dot[5] = {};
#pragma unroll 4
        for (int c = g; c < 64; c += 4) {
            float qv = __half2float(__ldg(qp + c * L_));
#pragma unroll
            for (int j = 0; j < 5; ++j)
                dot[j] += qv * __half2float(__ldg(kp + c*L_ + pc[j]));
        }
#pragma unroll
        for (int j = 0; j < 5; ++j) {
            dot[j] += __shfl_xor_sync(0xffffffffu, dot[j], 1);
            dot[j] += __shfl_xor_sync(0xffffffffu, dot[j], 2);
        }
        const float LVALID = logf(1.0f + 1e-6f);
        const float LINV   = logf(1e-6f);
        float lg5[5];
#pragma unroll
        for (int j = 0; j < 5; ++j) lg5[j] = v[j] ? dot[j]*0.125f + LVALID : LINV;
        float mx = lg5[0];
#pragma unroll
        for (int j = 1; j < 5; ++j) mx = fmaxf(mx, lg5[j]);
        float e[5], s = 0.f;
#pragma unroll
        for (int j = 0; j < 5; ++j) { e[j] = expf(lg5[j] - mx); s += e[j]; }
        float inv = 1.f / s;
        if (g == 0) {
#pragma unroll
            for (int j = 0; j < 5; ++j) satt[j][l] = v[j] ? e[j]*inv : 0.f;
        }
    }
    __syncthreads();

    const int tx = tid & 15, ty = tid >> 4;
    const int c0 = ty * 4, lx = tx * 4;
    float s1[4] = {}, s2[4] = {};
#pragma unroll
    for (int ci = 0; ci < 4; ++ci) {
        int c = c0 + ci;
        const __half* vp = g_xv + (size_t)(n*D_ + c) * L_;
        const __half* op = g_out1 + (size_t)(n*D_ + c) * L_ + l0;
        float* yp = g_y + (size_t)(n*D_ + c) * L_ + l0;
        float yv4[4];
#pragma unroll
        for (int lj = 0; lj < 4; ++lj) {
            int l = lx + lj, lgl = l0 + l;
            float r = 0.f;
#pragma unroll
            for (int j = 0; j < 5; ++j) {
                int pp = lgl + (j - 2) * dil;
                if ((unsigned)pp < (unsigned)L_)
                    r += satt[j][l] * __half2float(__ldg(vp + pp));
            }
            float yv = __half2float(op[l]) + r;
            yv4[lj] = yv;
            s1[ci] += yv; s2[ci] += yv * yv;
        }
        *(float4*)(yp + lx) = make_float4(yv4[0], yv4[1], yv4[2], yv4[3]);
    }
#pragma unroll
    for (int off = 8; off; off >>= 1)
#pragma unroll
        for (int ci = 0; ci < 4; ++ci) {
            s1[ci] += __shfl_xor_sync(0xffffffffu, s1[ci], off);
            s2[ci] += __shfl_xor_sync(0xffffffffu, s2[ci], off);
        }
    if (tx == 0) {
#pragma unroll
        for (int ci = 0; ci < 4; ++ci) {
            g_part[((n*D_ + c0 + ci)*128 + lblk)*2 + 0] = s1[ci];
            g_part[((n*D_ + c0 + ci)*128 + lblk)*2 + 1] = s2[ci];
        }
    }
}

__device__ __forceinline__ void mm_16x16(const float (*Ws)[64], const float (*Xs)[64],
                                         float acc[4][4], int ty4, int tx4) {
#pragma unroll 16
    for (int c = 0; c < 64; ++c) {
        const float4 a = *(const float4*)(&Ws[c][ty4]);
        const float4 b = *(const float4*)(&Xs[c][tx4]);
        acc[0][0] += a.x*b.x; acc[0][1] += a.x*b.y; acc[0][2] += a.x*b.z; acc[0][3] += a.x*b.w;
        acc[1][0] += a.y*b.x; acc[1][1] += a.y*b.y; acc[1][2] += a.y*b.z; acc[1][3] += a.y*b.w;
        acc[2][0] += a.z*b.x; acc[2][1] += a.z*b.y; acc[2][2] += a.z*b.z; acc[2][3] += a.z*b.w;
        acc[3][0] += a.w*b.x; acc[3][1] += a.w*b.y; acc[3][2] += a.w*b.z; acc[3][3] += a.w*b.w;
    }
}

__device__ void phaseC(char* dsm, int bidx, int layer,
                       const float* f1b, const float* f2b,
                       const float* cow, const float* cob, float* out, int last) {
    float (*Xs)[64] = (float(*)[64])dsm;
    float (*Ws)[64] = (float(*)[64])(dsm + 16384);
    float* sms = (float*)(dsm + 32768);
    float* srs = sms + 64;
    const int n = bidx >> 7, l0 = (bidx & 127) * 64;
    const int tid = threadIdx.x, ty4 = (tid >> 4) << 2, tx4 = (tid & 15) << 2;
    if (tid < 64) {
        float s = 0.f, s2 = 0.f;
        for (int bq = 0; bq < 128; ++bq) {
            s  += g_part[((n*D_ + tid)*128 + bq)*2 + 0];
            s2 += g_part[((n*D_ + tid)*128 + bq)*2 + 1];
        }
        float mean = s / (float)L_;
        float var = s2 / (float)L_ - mean*mean;
        sms[tid] = mean;
        srs[tid] = rsqrtf(var + 1e-5f);
    }
    __syncthreads();
    {
        const float* wsrc = g_f1T + (size_t)layer * 4096;
        for (int e = tid; e < 4096; e += 256) {
            int c = e >> 6, tt = e & 63;
            Xs[c][tt] = (g_y[(size_t)(n*D_ + c)*L_ + l0 + tt] - sms[c]) * srs[c];
            ((float*)Ws)[e] = wsrc[e];
        }
    }
    __syncthreads();
    float acc[4][4] = {};
    mm_16x16(Ws, Xs, acc, ty4, tx4);
    __syncthreads();
#pragma unroll
    for (int i = 0; i < 4; ++i)
#pragma unroll
        for (int j = 0; j < 4; ++j)
            Xs[ty4 + i][tx4 + j] = fmaxf(acc[i][j] + f1b[layer*64 + ty4 + i], 0.f);
    {
        const float* wsrc = g_f2T + (size_t)layer * 4096;
        for (int e = tid; e < 4096; e += 256) ((float*)Ws)[e] = wsrc[e];
    }
    __syncthreads();
    float a2[4][4] = {};
    mm_16x16(Ws, Xs, a2, ty4, tx4);
    float nv4[4][4];
#pragma unroll
    for (int i = 0; i < 4; ++i)
#pragma unroll
        for (int j = 0; j < 4; ++j) {
            int d = ty4 + i, l = l0 + tx4 + j;
            size_t o = (size_t)(n*D_ + d)*L_ + l;
            float nv = g_fra[o] + a2[i][j] + f2b[layer*64 + d];
            nv4[i][j] = nv;
            if (!last) {
                g_fra[o] = nv;
                g_fh[o] = __float2half(nv);
            }
        }
    if (last) {
        __syncthreads();
#pragma unroll
        for (int i = 0; i < 4; ++i)
#pragma unroll
            for (int j = 0; j < 4; ++j)
                Xs[ty4 + i][tx4 + j] = nv4[i][j];
        float (*Wt)[NC_] = (float(*)[NC_])(dsm + 16384);
        for (int e = tid; e < 64*NC_; e += 256) {
            int c = e / NC_, o = e % NC_;
            Wt[c][o] = cow[o*64 + c];
        }
        __syncthreads();
        const int ty = tid >> 4, tx = tid & 15;
        if (ty < 12) {
            const int oy4 = ty*4, ox4 = tx*4;
            float oc[4][4] = {};
#pragma unroll 16
            for (int c = 0; c < 64; ++c) {
                const float4 a = *(const float4*)(&Wt[c][oy4]);
                const float4 x4 = *(const float4*)(&Xs[c][ox4]);
                oc[0][0]+=a.x*x4.x; oc[0][1]+=a.x*x4.y; oc[0][2]+=a.x*x4.z; oc[0][3]+=a.x*x4.w;
                oc[1][0]+=a.y*x4.x; oc[1][1]+=a.y*x4.y; oc[1][2]+=a.y*x4.z; oc[1][3]+=a.y*x4.w;
                oc[2][0]+=a.z*x4.x; oc[2][1]+=a.z*x4.y; oc[2][2]+=a.z*x4.z; oc[2][3]+=a.z*x4.w;
                oc[3][0]+=a.w*x4.x; oc[3][1]+=a.w*x4.y; oc[3][2]+=a.w*x4.z; oc[3][3]+=a.w*x4.w;
            }
#pragma unroll
            for (int i = 0; i < 4; ++i)
#pragma unroll
                for (int j = 0; j < 4; ++j) {
                    int o = oy4 + i, l = l0 + ox4 + j;
                    out[(size_t)(n*NC_ + o)*L_ + l] = oc[i][j] + cob[o];
                }
        }
    }
}

__global__ void __launch_bounds__(256, 2) layers_kernel(
        const float* __restrict__ convb, const float* __restrict__ qb,
        const float* __restrict__ kb,   const float* __restrict__ vb,
        const float* __restrict__ f1b,  const float* __restrict__ f2b,
        const float* __restrict__ cow,  const float* __restrict__ cob,
        float* __restrict__ out) {
    extern __shared__ char dsm[];
    const int bidx = blockIdx.x;
    const unsigned ep = *((volatile unsigned*)&g_epoch);
    for (int layer = 0; layer < NL_; ++layer) {
        const int dil = 1 << layer;
        phaseA(dsm, bidx, layer, dil, ep, convb, qb, kb, vb);
        gbar();
        phaseB(dsm, bidx, dil);
        gbar();
        phaseC(dsm, bidx, layer, f1b, f2b, cow, cob, out, layer == NL_ - 1);
        if (layer < NL_ - 1) gbar();
    }
}

// ---------------- host side ----------------
extern "C" void kernel_launch(void* const* d_in, const int* in_sizes, int n_in,
                              void* d_out, int out_size) {
    (void)in_sizes; (void)n_in; (void)out_size;
    const float* x     = (const float*)d_in[0];
    const int*   t     = (const int*)  d_in[1];
    const float* event = (const float*)d_in[2];
    const float* tw1   = (const float*)d_in[3];
    const float* tb1   = (const float*)d_in[4];
    const float* tw2   = (const float*)d_in[5];
    const float* tb2   = (const float*)d_in[6];
    const float* tpw   = (const float*)d_in[7];
    const float* tpb   = (const float*)d_in[8];
    const float* ciw   = (const float*)d_in[9];
    const float* cib   = (const float*)d_in[10];
    const float* cow   = (const float*)d_in[11];
    const float* cob   = (const float*)d_in[12];
    const float* lcw   = (const float*)d_in[13];
    const float* lcb   = (const float*)d_in[14];
    const float* qw    = (const float*)d_in[15];
    const float* qb    = (const float*)d_in[16];
    const float* kw    = (const float*)d_in[17];
    const float* kb    = (const float*)d_in[18];
    const float* vw    = (const float*)d_in[19];
    const float* vb    = (const float*)d_in[20];
    const float* f1w   = (const float*)d_in[21];
    const float* f1b   = (const float*)d_in[22];
    const float* f2w   = (const float*)d_in[23];
    const float* f2b   = (const float*)d_in[24];

    static cudaStream_t s2 = nullptr;
    static cudaEvent_t ev_fork = nullptr, ev_join = nullptr;
    if (!s2) {
        cudaStreamCreateWithFlags(&s2, cudaStreamNonBlocking);
        cudaEventCreateWithFlags(&ev_fork, cudaEventDisableTiming);
        cudaEventCreateWithFlags(&ev_join, cudaEventDisableTiming);
        cudaFuncSetAttribute(layers_kernel, cudaFuncAttributeMaxDynamicSharedMemorySize, LA_SMEM);
        cudaFuncSetAttribute(gemm_fp16_kernel, cudaFuncAttributeMaxDynamicSharedMemorySize, GM_SMEM);
    }

    pack_wp_kernel<<<(M_*CR_)/256, 256>>>(qw, kw);
    xt_kernel<<<dim3(L_/32, CR_/32, B_), 256>>>(x);
    cudaEventRecord(ev_fork, 0);

    // forked stream: GEMM slices for layers 1..7 overlap with the layer loop
    cudaStreamWaitEvent(s2, ev_fork, 0);
    gemm_fp16_kernel<<<dim3(NL_ - 1, NCOL_/GM_BN), 256, GM_SMEM, s2>>>(1);
    cudaEventRecord(ev_join, s2);

    pack_aw_kernel<<<(NL_*8*64*64)/256, 256>>>(lcw, qw, kw, vw, f1w, f2w);
    temb1_kernel<<<dim3(64, B_), 256>>>(t, tw1, tb1);
    temb2_kernel<<<dim3(64, B_), 256>>>(tw2, tb2);
    gemm_fp16_kernel<<<dim3(1, NCOL_/GM_BN), 256, GM_SMEM>>>(0);   // layer-0 slice
    tembp_kernel<<<dim3(8, B_), 256>>>(tpw, tpb);
    conv_in_kernel<<<dim3(L_/64, B_), 256>>>(event, ciw, cib);

    layers_kernel<<<NBLK, 256, LA_SMEM>>>(lcb, qb, kb, vb, f1b, f2b, cow, cob, (float*)d_out);
    cudaStreamWaitEvent(0, ev_join, 0);   // join forked stream into the graph
}

// round 16
// speedup vs baseline: 1.0536x; 1.0536x over previous
#include <cuda_runtime.h>
#include <cuda_bf16.h>
#include <cuda_fp16.h>
#include <math.h>
#include <stdint.h>

#define B_  2
#define L_  8192
#define D_  64
#define CR_ 2048
#define NC_ 48
#define TE_ 512
#define NL_ 8
#define M_  1024
#define NCOL_ (B_*L_)
#define NBLK 256
#define NGRP 16
#define GRPSZ (NBLK/NGRP)

// ---------------- scratch ----------------
__device__ __half g_Wp[(size_t)M_*CR_];
__device__ __half g_Xp[(size_t)NCOL_*CR_];
__device__ __half g_QKCh[(size_t)M_*NCOL_];
__device__ __half g_AW[NL_*8*64*64];     // [i][slot][m][k]; slots: taps{0,1,3,4,2},q,k,v
__device__ __half g_fh[B_*D_*L_];
__device__ float g_f1T [NL_*64*64];
__device__ float g_f2T [NL_*64*64];
__device__ float g_fra [B_*D_*L_];
__device__ __half g_xq  [B_*D_*L_];
__device__ __half g_xk  [B_*D_*L_];
__device__ __half g_xv  [B_*D_*L_];
__device__ __half g_out1[B_*D_*L_];
__device__ float g_part[B_*D_*128*2];
__device__ float g_tproj[B_*D_];
__device__ float g_t1[B_*TE_];
__device__ float g_t2[B_*TE_];
__device__ unsigned g_bgrp[NGRP];
__device__ unsigned g_barc = 0;
__device__ unsigned g_barg = 0;

__device__ __forceinline__ uint32_t smem_u32(const void* p) {
    return (uint32_t)__cvta_generic_to_shared(p);
}
__device__ __forceinline__ void ldsm_x4(uint32_t* r, uint32_t addr) {
    asm volatile("ldmatrix.sync.aligned.m8n8.x4.shared.b16 {%0,%1,%2,%3}, [%4];"
                 : "=r"(r[0]), "=r"(r[1]), "=r"(r[2]), "=r"(r[3]) : "r"(addr));
}
__device__ __forceinline__ void ldsm_x4t(uint32_t* r, uint32_t addr) {
    asm volatile("ldmatrix.sync.aligned.m8n8.x4.trans.shared.b16 {%0,%1,%2,%3}, [%4];"
                 : "=r"(r[0]), "=r"(r[1]), "=r"(r[2]), "=r"(r[3]) : "r"(addr));
}
__device__ __forceinline__ void mma_fp16(float c[4], uint32_t a0, uint32_t a1, uint32_t a2,
                                         uint32_t a3, uint32_t b0, uint32_t b1) {
    asm volatile("mma.sync.aligned.m16n8k16.row.col.f32.f16.f16.f32 "
                 "{%0,%1,%2,%3}, {%4,%5,%6,%7}, {%8,%9}, {%0,%1,%2,%3};"
                 : "+f"(c[0]), "+f"(c[1]), "+f"(c[2]), "+f"(c[3])
                 : "r"(a0), "r"(a1), "r"(a2), "r"(a3), "r"(b0), "r"(b1));
}
__device__ __forceinline__ void cp16(uint32_t saddr, const void* gptr) {
    asm volatile("cp.async.cg.shared.global [%0], [%1], 16;" :: "r"(saddr), "l"(gptr));
}
#define CP_COMMIT() asm volatile("cp.async.commit_group;")
#define CP_WAIT1() asm volatile("cp.async.wait_group 1;")
#define CP_WAIT0() asm volatile("cp.async.wait_group 0;")

// two-level grid barrier with cumulative counters
__device__ __forceinline__ void gbar() {
    __syncthreads();
    if (threadIdx.x == 0) {
        __threadfence();
        const unsigned gen = *((volatile unsigned*)&g_barg);
        const int grp = blockIdx.x & (NGRP - 1);
        if (atomicAdd(&g_bgrp[grp], 1u) == (gen + 1) * GRPSZ - 1) {
            if (atomicAdd(&g_barc, 1u) == (gen + 1) * NGRP - 1) {
                __threadfence();
                atomicAdd(&g_barg, 1u);
            }
        }
        while (*((volatile unsigned*)&g_barg) == gen) { }
        __threadfence();
    }
    __syncthreads();
}

// ================== fp16 HMMA cross GEMM ==================
#define GM_BM 128
#define GM_BN 128
#define GM_BK 32
#define GM_NT (CR_/GM_BK)
#define APAD 40
#define GM_ST 3
#define GM_TILE (128*APAD)
#define GM_SMEM (GM_ST*2*GM_TILE*2)

__global__ void __launch_bounds__(256, 2) gemm_fp16_kernel() {
    extern __shared__ __half gsm[];
    __half* As = gsm;
    __half* Bs = gsm + GM_ST*GM_TILE;
    const int tid = threadIdx.x, lane = tid & 31, wid = tid >> 5;
    const int wm = wid >> 2, wn = wid & 3;
    const int m0 = blockIdx.x * GM_BM;
    const int col0 = blockIdx.y * GM_BN;
    const int ldr = tid >> 1, ldc = (tid & 1) * 2;

    float acc[4][4][4];
#pragma unroll
    for (int i = 0; i < 4; ++i)
#pragma unroll
        for (int j = 0; j < 4; ++j)
#pragma unroll
            for (int q = 0; q < 4; ++q) acc[i][j][q] = 0.f;

    const int lrow = lane & 15, lhalf = lane >> 4;

    auto load_tile = [&](int kt, int buf) {
        const size_t gk = (size_t)kt * GM_BK;
        __half* ab = As + buf * GM_TILE;
        __half* bb = Bs + buf * GM_TILE;
#pragma unroll
        for (int s = 0; s < 2; ++s) {
            int c = ldc + s;
            cp16(smem_u32(ab + ldr * APAD + c * 8),
                 g_Wp + (size_t)(m0 + ldr) * CR_ + gk + c * 8);
            cp16(smem_u32(bb + ldr * APAD + c * 8),
                 g_Xp + (size_t)(col0 + ldr) * CR_ + gk + c * 8);
        }
        CP_COMMIT();
    };

    load_tile(0, 0);
    load_tile(1, 1);
    for (int kt = 0; kt < GM_NT; ++kt) {
        const int cur = kt % GM_ST;
        CP_WAIT1();
        __syncthreads();
        if (kt + 2 < GM_NT) load_tile(kt + 2, (kt + 2) % GM_ST);
        const __half* ab = As + cur * GM_TILE;
        const __half* bb = Bs + cur * GM_TILE;
#pragma unroll
        for (int kk2 = 0; kk2 < 2; ++kk2) {
            uint32_t a[4][4];
#pragma unroll
            for (int mt = 0; mt < 4; ++mt)
                ldsm_x4(a[mt], smem_u32(ab + (wm*64 + mt*16 + lrow) * APAD + kk2*16 + lhalf*8));
            uint32_t b[4][2];
#pragma unroll
            for (int nb2 = 0; nb2 < 2; ++nb2) {
                uint32_t r[4];
                ldsm_x4(r, smem_u32(bb + (wn*32 + nb2*16 + lrow) * APAD + kk2*16 + lhalf*8));
                b[nb2*2 + 0][0] = r[0]; b[nb2*2 + 0][1] = r[2];
                b[nb2*2 + 1][0] = r[1]; b[nb2*2 + 1][1] = r[3];
            }
#pragma unroll
            for (int mt = 0; mt < 4; ++mt)
#pragma unroll
                for (int nt = 0; nt < 4; ++nt)
                    mma_fp16(acc[mt][nt], a[mt][0], a[mt][1], a[mt][2], a[mt][3],
                             b[nt][0], b[nt][1]);
        }
    }
    const int grp = lane >> 2, qd = (lane & 3) * 2;
#pragma unroll
    for (int mt = 0; mt < 4; ++mt)
#pragma unroll
        for (int nt = 0; nt < 4; ++nt) {
            int m = m0 + wm*64 + mt*16 + grp;
            int n = col0 + wn*32 + nt*8 + qd;
            *(__half2*)(g_QKCh + (size_t)m * NCOL_ + n)       = __floats2half2_rn(acc[mt][nt][0], acc[mt][nt][1]);
            *(__half2*)(g_QKCh + (size_t)(m + 8) * NCOL_ + n) = __floats2half2_rn(acc[mt][nt][2], acc[mt][nt][3]);
        }
}

// ---------------- packing ----------------
__global__ void pack_wp_kernel(const float* __restrict__ qw, const float* __restrict__ kw) {
    int idx = blockIdx.x * 256 + threadIdx.x;
    int m = idx >> 11, c = idx & 2047;
    int i = m >> 7, r = m & 127, s = r >> 6, d = r & 63;
    const float* src = s ? kw : qw;
    g_Wp[(size_t)m * CR_ + c] = __float2half(src[(i*64 + d)*2112 + 64 + c]);
}

__global__ void __launch_bounds__(256) xt_kernel(const float* __restrict__ x) {
    __shared__ float ts[32][33];
    const int lb = blockIdx.x * 32, kb = blockIdx.y * 32, n = blockIdx.z;
    const int tx = threadIdx.x & 31, ty = threadIdx.x >> 5;
#pragma unroll
    for (int r = ty; r < 32; r += 8)
        ts[r][tx] = x[((size_t)n * CR_ + kb + r) * L_ + lb + tx];
    __syncthreads();
#pragma unroll
    for (int r = ty; r < 32; r += 8)
        g_Xp[(size_t)(n * L_ + lb + r) * CR_ + kb + tx] = __float2half(ts[tx][r]);
}

__global__ void pack_aw_kernel(const float* __restrict__ convw, const float* __restrict__ qw,
                               const float* __restrict__ kw,   const float* __restrict__ vw,
                               const float* __restrict__ f1w,  const float* __restrict__ f2w) {
    int idx = blockIdx.x * 256 + threadIdx.x;
    if (idx < NL_*8*64*64) {
        int c = idx & 63, m = (idx >> 6) & 63, s = (idx >> 12) & 7, i = idx >> 15;
        const int tapmap[5] = {0, 1, 3, 4, 2};
        float v;
        if (s < 5)      v = convw[((i*64 + m)*64 + c)*5 + tapmap[s]];
        else if (s == 5) v = qw[(i*64 + m)*2112 + c];
        else if (s == 6) v = kw[(i*64 + m)*2112 + c];
        else             v = vw[(i*64 + m)*64 + c];
        g_AW[(size_t)(i*8 + s) * 4096 + m*64 + c] = __float2half(v);
    }
    if (idx < NL_*64*64) {
        int d = idx & 63, c = (idx >> 6) & 63, i = idx >> 12;
        g_f1T[idx] = f1w[(i*64 + d)*64 + c];
        g_f2T[idx] = f2w[(i*64 + d)*64 + c];
    }
}

// ---------------- timestep embedding ----------------
__global__ void temb1_kernel(const int* __restrict__ t, const float* __restrict__ w1,
                             const float* __restrict__ b1) {
    __shared__ float se[TE_];
    const int n = blockIdx.y, tid = threadIdx.x;
    const float tv = (float)t[n];
    if (tid < 256) {
        float f = expf((float)tid * (-logf(10000.0f) / 255.0f));
        se[tid] = sinf(tv * f);
        se[tid + 256] = cosf(tv * f);
    }
    __syncthreads();
    const int w = tid >> 5, lane = tid & 31;
    const int o = blockIdx.x * 8 + w;
    const float* wr = w1 + (size_t)o * TE_;
    float s = 0.f;
    for (int c = lane; c < TE_; c += 32) s += se[c] * wr[c];
#pragma unroll
    for (int off = 16; off; off >>= 1) s += __shfl_xor_sync(0xffffffffu, s, off);
    if (!lane) { s += b1[o]; g_t1[n*TE_ + o] = s / (1.f + expf(-s)); }
}
__global__ void temb2_kernel(const float* __restrict__ w2, const float* __restrict__ b2) {
    __shared__ float se[TE_];
    const int n = blockIdx.y, tid = threadIdx.x;
    se[tid] = g_t1[n*TE_ + tid];
    se[tid + 256] = g_t1[n*TE_ + tid + 256];
    __syncthreads();
    const int w = tid >> 5, lane = tid & 31;
    const int o = blockIdx.x * 8 + w;
    const float* wr = w2 + (size_t)o * TE_;
    float s = 0.f;
    for (int c = lane; c < TE_; c += 32) s += se[c] * wr[c];
#pragma unroll
    for (int off = 16; off; off >>= 1) s += __shfl_xor_sync(0xffffffffu, s, off);
    if (!lane) g_t2[n*TE_ + o] = s + b2[o];
}
__global__ void tembp_kernel(const float* __restrict__ wp, const float* __restrict__ bp) {
    __shared__ float se[TE_];
    const int n = blockIdx.y, tid = threadIdx.x;
    {
        float v0 = g_t2[n*TE_ + tid], v1 = g_t2[n*TE_ + tid + 256];
        se[tid]       = v0 / (1.f + expf(-v0));
        se[tid + 256] = v1 / (1.f + expf(-v1));
    }
    __syncthreads();
    const int w = tid >> 5, lane = tid & 31;
    const int o = blockIdx.x * 8 + w;
    const float* wr = wp + (size_t)o * TE_;
    float s = 0.f;
    for (int c = lane; c < TE_; c += 32) s += se[c] * wr[c];
#pragma unroll
    for (int off = 16; off; off >>= 1) s += __shfl_xor_sync(0xffffffffu, s, off);
    if (!lane) g_tproj[n*D_ + o] = s + bp[o];
}

// ---------------- conv_in ----------------
__global__ void __launch_bounds__(256) conv_in_kernel(const float* __restrict__ event,
                                                      const float* __restrict__ w,
                                                      const float* __restrict__ b) {
    __shared__ float Et[NC_][64];
    __shared__ float Wt[NC_][64];
    const int n = blockIdx.y, l0 = blockIdx.x * 64;
    const int tid = threadIdx.x, ty4 = (tid >> 4) << 2, tx4 = (tid & 15) << 2;
    for (int e = tid; e < NC_*64; e += 256) {
        int c = e >> 6, tt = e & 63;
        Et[c][tt] = event[(n*NC_ + c)*L_ + l0 + tt];
        Wt[c][tt] = w[tt*NC_ + c];
    }
    __syncthreads();
    float acc[4][4] = {};
#pragma unroll
    for (int c = 0; c < NC_; ++c) {
        const float4 a = *(const float4*)(&Wt[c][ty4]);
        const float4 x4 = *(const float4*)(&Et[c][tx4]);
        acc[0][0]+=a.x*x4.x; acc[0][1]+=a.x*x4.y; acc[0][2]+=a.x*x4.z; acc[0][3]+=a.x*x4.w;
        acc[1][0]+=a.y*x4.x; acc[1][1]+=a.y*x4.y; acc[1][2]+=a.y*x4.z; acc[1][3]+=a.y*x4.w;
        acc[2][0]+=a.z*x4.x; acc[2][1]+=a.z*x4.y; acc[2][2]+=a.z*x4.z; acc[2][3]+=a.z*x4.w;
        acc[3][0]+=a.w*x4.x; acc[3][1]+=a.w*x4.y; acc[3][2]+=a.w*x4.z; acc[3][3]+=a.w*x4.w;
    }
#pragma unroll
    for (int i = 0; i < 4; ++i)
#pragma unroll
        for (int j = 0; j < 4; ++j) {
            int d = ty4 + i, l = l0 + tx4 + j;
            size_t o = (size_t)(n*D_ + d)*L_ + l;
            float v = acc[i][j] + b[d] + g_tproj[n*D_ + d];
            g_fra[o] = v;
            g_fh[o] = __float2half(v);
        }
}

// ================== persistent layers kernel (88KB, 2/SM) ==================
#define LA_SMEM (40960 + 49152)
#define YS_OFF 65536    // 16KB y-tile; inside phaseA's smB region, free during B/C

__device__ __forceinline__ void mm64(float acc[2][4][4], uint32_t Ah,
                                     uint32_t Bh, int wm, int wn, int lane) {
    const int lrow = lane & 15, lhalf = lane >> 4;
    const int bk = (lane & 7) + (((lane >> 3) & 1) << 3);
    const int bn8 = (lane >> 4) << 3;
#pragma unroll
    for (int k0 = 0; k0 < 4; ++k0) {
        uint32_t a[2][4];
#pragma unroll
        for (int mt = 0; mt < 2; ++mt) {
            int m = wm*32 + mt*16 + lrow;
            int ch = (k0*2 + lhalf) ^ (m & 7);
            ldsm_x4(a[mt], Ah + m*128 + ch*16);
        }
        uint32_t b[4][2];
#pragma unroll
        for (int ng = 0; ng < 2; ++ng) {
            int k = k0*16 + bk;
            int n = wn*32 + ng*16 + bn8;
            int ch = (n >> 3) ^ (k & 7);
            uint32_t r[4];
            ldsm_x4t(r, Bh + k*256 + ch*16);
            b[ng*2 + 0][0] = r[0]; b[ng*2 + 0][1] = r[1];
            b[ng*2 + 1][0] = r[2]; b[ng*2 + 1][1] = r[3];
        }
#pragma unroll
        for (int mt = 0; mt < 2; ++mt)
#pragma unroll
            for (int nt = 0; nt < 4; ++nt)
                mma_fp16(acc[mt][nt], a[mt][0], a[mt][1], a[mt][2], a[mt][3],
                         b[nt][0], b[nt][1]);
    }
}

__device__ void phaseA(char* dsm, int bidx, int layer, int dil,
                       const float* convb, const float* qb,
                       const float* kb, const float* vb) {
    char* smA = dsm;             // 5 x 8KB
    char* smB = dsm + 40960;     // 3 x 16KB
    const int tid = threadIdx.x, lane = tid & 31, wid = tid >> 5;
    const int wm = wid >> 2, wn = wid & 3;
    const int l0 = (bidx & 63) * 128;
    const int nb = (bidx >> 6) & 1;
    const int z  = bidx >> 7;
    const __half* fh = g_fh + (size_t)nb * D_ * L_;
    const float* fb = g_fra + (size_t)nb * D_ * L_;

    auto loadA = [&](int slot, int buf) {
        const __half* src = g_AW + (size_t)(layer*8 + slot) * 4096;
        char* dh = smA + buf * 8192;
#pragma unroll
        for (int e = tid; e < 512; e += 256) {
            int m = e >> 3, c = e & 7;
            int off = m*128 + ((c ^ (m & 7)) << 4);
            cp16(smem_u32(dh + off), src + m*64 + c*8);
        }
    };
    auto loadB = [&](int shift, int buf) {
        char* dh = smB + buf * 16384;
        if ((shift & 7) == 0) {
#pragma unroll
            for (int e = tid; e < 1024; e += 256) {
                int k = e >> 4, c = e & 15;
                int gl = l0 + c*8 + shift;
                int off = k*256 + ((c ^ (k & 7)) << 4);
                if (gl >= 0 && gl + 8 <= L_) {
                    cp16(smem_u32(dh + off), fh + (size_t)k * L_ + gl);
                } else {
                    __half* ph = (__half*)(dh + off);
#pragma unroll
                    for (int u = 0; u < 8; ++u) {
                        int l = gl + u;
                        ph[u] = ((unsigned)l < (unsigned)L_) ? fh[(size_t)k * L_ + l] : __half(0.f);
                    }
                }
            }
        } else {
#pragma unroll
            for (int e = tid; e < 1024; e += 256) {
                int k = e >> 4, c = e & 15;
                int gl = l0 + c*8 + shift;
                int off = k*256 + ((c ^ (k & 7)) << 4);
                const float* src = fb + (size_t)k * L_;
                __half hb[8];
#pragma unroll
                for (int u = 0; u < 8; ++u) {
                    int l = gl + u;
                    hb[u] = __float2half(((unsigned)l < (unsigned)L_) ? __ldg(src + l) : 0.f);
                }
                *(uint4*)(dh + off) = *(uint4*)hb;
            }
        }
    };

    float acc[2][4][4];
#pragma unroll
    for (int i = 0; i < 2; ++i)
#pragma unroll
        for (int j = 0; j < 4; ++j)
#pragma unroll
            for (int q = 0; q < 4; ++q) acc[i][j][q] = 0.f;

    const int grp = lane >> 2, qd = (lane & 3) * 2;
    auto epilogue = [&](__half* dst, const float* bias, const __half* qkc) {
#pragma unroll
        for (int mt = 0; mt < 2; ++mt)
#pragma unroll
            for (int nt = 0; nt < 4; ++nt) {
                int m = wm*32 + mt*16 + grp;
                int n = wn*32 + nt*8 + qd;
                float v0 = acc[mt][nt][0] + bias[m];
                float v1 = acc[mt][nt][1] + bias[m];
                float v2 = acc[mt][nt][2] + bias[m + 8];
                float v3 = acc[mt][nt][3] + bias[m + 8];
                if (qkc) {
                    __half2 e0 = *(const __half2*)(qkc + (size_t)m * NCOL_ + n);
                    __half2 e1 = *(const __half2*)(qkc + (size_t)(m + 8) * NCOL_ + n);
                    v0 += __low2float(e0); v1 += __high2float(e0);
                    v2 += __low2float(e1); v3 += __high2float(e1);
                }
                *(__half2*)(dst + (size_t)(nb*D_ + m) * L_ + l0 + n)     = __floats2half2_rn(v0, v1);
                *(__half2*)(dst + (size_t)(nb*D_ + m + 8) * L_ + l0 + n) = __floats2half2_rn(v2, v3);
                acc[mt][nt][0] = acc[mt][nt][1] = acc[mt][nt][2] = acc[mt][nt][3] = 0.f;
            }
    };

    if (z == 0) {
        const int tapshift[5] = {-2*dil, -dil, dil, 2*dil, 0};
#pragma unroll
        for (int s = 0; s < 5; ++s) loadA(s, s);
        CP_COMMIT();
        loadB(tapshift[0], 0); CP_COMMIT();
        loadB(tapshift[1], 1); CP_COMMIT();
        for (int it = 0; it < 5; ++it) {
            if (it < 4) CP_WAIT1();
            else CP_WAIT0();
            __syncthreads();
            if (it + 2 < 5) { loadB(tapshift[it + 2], (it + 2) % 3); CP_COMMIT(); }
            mm64(acc, smem_u32(smA + it * 8192), smem_u32(smB + (it % 3) * 16384),
                 wm, wn, lane);
        }
        epilogue(g_out1, convb + layer*64, nullptr);
    } else {
        loadB(0, 0);
        loadA(5, 0); loadA(6, 1); loadA(7, 2);
        CP_COMMIT();
        CP_WAIT0();
        __syncthreads();
        const uint32_t Bh = smem_u32(smB);
        mm64(acc, smem_u32(smA), Bh, wm, wn, lane);
        epilogue(g_xq, qb + layer*64, g_QKCh + (size_t)(layer*2)*64*NCOL_ + nb*L_ + l0);
        mm64(acc, smem_u32(smA + 8192), Bh, wm, wn, lane);
        epilogue(g_xk, kb + layer*64, g_QKCh + (size_t)(layer*2 + 1)*64*NCOL_ + nb*L_ + l0);
        mm64(acc, smem_u32(smA + 16384), Bh, wm, wn, lane);
        epilogue(g_xv, vb + layer*64, nullptr);
    }
}

// ---------------- phaseB: attention; y-tile kept in smem for phaseC ----------------
__device__ void phaseB(char* dsm, int bidx, int dil) {
    float (*satt)[64] = (float(*)[64])dsm;
    float (*ys)[64] = (float(*)[64])(dsm + YS_OFF);
    const int n = bidx >> 7, lblk = bidx & 127, l0 = lblk * 64;
    const int tid = threadIdx.x;
    {
        const int g = tid & 3, l = tid >> 2;
        const int lg = l0 + l;
        const __half* qp = g_xq + (size_t)n * D_ * L_ + lg;
        const __half* kp = g_xk + (size_t)n * D_ * L_;
        bool v[5]; int pc[5];
#pragma unroll
        for (int j = 0; j < 5; ++j) {
            int p = lg + (j - 2) * dil;
            v[j] = ((unsigned)p < (unsigned)L_);
            pc[j] = v[j] ? p : lg;
        }
        float dot[5] = {};
#pragma unroll 4
        for (int c = g; c < 64; c += 4) {
            float qv = __half2float(__ldg(qp + c * L_));
#pragma unroll
            for (int j = 0; j < 5; ++j)
                dot[j] += qv * __half2float(__ldg(kp + c*L_ + pc[j]));
        }
#pragma unroll
        for (int j = 0; j < 5; ++j) {
            dot[j] += __shfl_xor_sync(0xffffffffu, dot[j], 1);
            dot[j] += __shfl_xor_sync(0xffffffffu, dot[j], 2);
        }
        const float LVALID = logf(1.0f + 1e-6f);
        const float LINV   = logf(1e-6f);
        float lg5[5];
#pragma unroll
        for (int j = 0; j < 5; ++j) lg5[j] = v[j] ? dot[j]*0.125f + LVALID : LINV;
        float mx = lg5[0];
#pragma unroll
        for (int j = 1; j < 5; ++j) mx = fmaxf(mx, lg5[j]);
        float e[5], s = 0.f;
#pragma unroll
        for (int j = 0; j < 5; ++j) { e[j] = expf(lg5[j] - mx); s += e[j]; }
        float inv = 1.f / s;
        if (g == 0) {
#pragma unroll
            for (int j = 0; j < 5; ++j) satt[j][l] = v[j] ? e[j]*inv : 0.f;
        }
    }
    __syncthreads();

    const int tx = tid & 15, ty = tid >> 4;
    const int c0 = ty * 4, lx = tx * 4;
    float s1[4] = {}, s2[4] = {};
#pragma unroll
    for (int ci = 0; ci < 4; ++ci) {
        int c = c0 + ci;
        const __half* vp = g_xv + (size_t)(n*D_ + c) * L_;
        const __half* op = g_out1 + (size_t)(n*D_ + c) * L_ + l0;
#pragma unroll
        for (int lj = 0; lj < 4; ++lj) {
            int l = lx + lj, lgl = l0 + l;
            float r = 0.f;
#pragma unroll
            for (int j = 0; j < 5; ++j) {
                int pp = lgl + (j - 2) * dil;
                if ((unsigned)pp < (unsigned)L_)
                    r += satt[j][l] * __half2float(__ldg(vp + pp));
            }
            float yv = __half2float(op[l]) + r;
            ys[c][l] = yv;
            s1[ci] += yv; s2[ci] += yv * yv;
        }
    }
#pragma unroll
    for (int off = 8; off; off >>= 1)
#pragma unroll
        for (int ci = 0; ci < 4; ++ci) {
            s1[ci] += __shfl_xor_sync(0xffffffffu, s1[ci], off);
            s2[ci] += __shfl_xor_sync(0xffffffffu, s2[ci], off);
        }
    if (tx == 0) {
#pragma unroll
        for (int ci = 0; ci < 4; ++ci) {
            g_part[((n*D_ + c0 + ci)*128 + lblk)*2 + 0] = s1[ci];
            g_part[((n*D_ + c0 + ci)*128 + lblk)*2 + 1] = s2[ci];
        }
    }
}

__device__ __forceinline__ void mm_16x16(const float (*Ws)[64], const float (*Xs)[64],
                                         float acc[4][4], int ty4, int tx4) {
#pragma unroll 16
    for (int c = 0; c < 64; ++c) {
        const float4 a = *(const float4*)(&Ws[c][ty4]);
        const float4 b = *(const float4*)(&Xs[c][tx4]);
        acc[0][0] += a.x*b.x; acc[0][1] += a.x*b.y; acc[0][2] += a.x*b.z; acc[0][3] += a.x*b.w;
        acc[1][0] += a.y*b.x; acc[1][1] += a.y*b.y; acc[1][2] += a.y*b.z; acc[1][3] += a.y*b.w;
        acc[2][0] += a.z*b.x; acc[2][1] += a.z*b.y; acc[2][2] += a.z*b.z; acc[2][3] += a.z*b.w;
        acc[3][0] += a.w*b.x; acc[3][1] += a.w*b.y; acc[3][2] += a.w*b.z; acc[3][3] += a.w*b.w;
    }
}

__device__ void phaseC(char* dsm, int bidx, int layer,
                       const float* f1b, const float* f2b,
                       const float* cow, const float* cob, float* out, int last) {
    float (*Xs)[64] = (float(*)[64])dsm;
    float (*Ws)[64] = (float(*)[64])(dsm + 16384);
    float* sms = (float*)(dsm + 32768);
    float* srs = sms + 64;
    float (*ys)[64] = (float(*)[64])(dsm + YS_OFF);
    const int n = bidx >> 7, l0 = (bidx & 127) * 64;
    const int tid = threadIdx.x, ty4 = (tid >> 4) << 2, tx4 = (tid & 15) << 2;
    if (tid < 64) {
        float s = 0.f, s2 = 0.f;
        for (int bq = 0; bq < 128; ++bq) {
            s  += g_part[((n*D_ + tid)*128 + bq)*2 + 0];
            s2 += g_part[((n*D_ + tid)*128 + bq)*2 + 1];
        }
        float mean = s / (float)L_;
        float var = s2 / (float)L_ - mean*mean;
        sms[tid] = mean;
        srs[tid] = rsqrtf(var + 1e-5f);
    }
    __syncthreads();
    {
        const float* wsrc = g_f1T + (size_t)layer * 4096;
        for (int e = tid; e < 4096; e += 256) {
            int c = e >> 6, tt = e & 63;
            Xs[c][tt] = (ys[c][tt] - sms[c]) * srs[c];
            ((float*)Ws)[e] = wsrc[e];
        }
    }
    __syncthreads();
    float acc[4][4] = {};
    mm_16x16(Ws, Xs, acc, ty4, tx4);
    __syncthreads();
#pragma unroll
    for (int i = 0; i < 4; ++i)
#pragma unroll
        for (int j = 0; j < 4; ++j)
            Xs[ty4 + i][tx4 + j] = fmaxf(acc[i][j] + f1b[layer*64 + ty4 + i], 0.f);
    {
        const float* wsrc = g_f2T + (size_t)layer * 4096;
        for (int e = tid; e < 4096; e += 256) ((float*)Ws)[e] = wsrc[e];
    }
    __syncthreads();
    float a2[4][4] = {};
    mm_16x16(Ws, Xs, a2, ty4, tx4);
    float nv4[4][4];
#pragma unroll
    for (int i = 0; i < 4; ++i)
#pragma unroll
        for (int j = 0; j < 4; ++j) {
            int d = ty4 + i, l = l0 + tx4 + j;
            size_t o = (size_t)(n*D_ + d)*L_ + l;
            float nv = g_fra[o] + a2[i][j] + f2b[layer*64 + d];
            nv4[i][j] = nv;
            if (!last) {
                g_fra[o] = nv;
                g_fh[o] = __float2half(nv);
            }
        }
    if (last) {
        __syncthreads();
#pragma unroll
        for (int i = 0; i < 4; ++i)
#pragma unroll
            for (int j = 0; j < 4; ++j)
                Xs[ty4 + i][tx4 + j] = nv4[i][j];
        float (*Wt)[NC_] = (float(*)[NC_])(dsm + 16384);
        for (int e = tid; e < 64*NC_; e += 256) {
            int c = e / NC_, o = e % NC_;
            Wt[c][o] = cow[o*64 + c];
        }
        __syncthreads();
        const int ty = tid >> 4, tx = tid & 15;
        if (ty < 12) {
            const int oy4 = ty*4, ox4 = tx*4;
            float oc[4][4] = {};
#pragma unroll 16
            for (int c = 0; c < 64; ++c) {
                const float4 a = *(const float4*)(&Wt[c][oy4]);
                const float4 x4 = *(const float4*)(&Xs[c][ox4]);
                oc[0][0]+=a.x*x4.x; oc[0][1]+=a.x*x4.y; oc[0][2]+=a.x*x4.z; oc[0][3]+=a.x*x4.w;
                oc[1][0]+=a.y*x4.x; oc[1][1]+=a.y*x4.y; oc[1][2]+=a.y*x4.z; oc[1][3]+=a.y*x4.w;
                oc[2][0]+=a.z*x4.x; oc[2][1]+=a.z*x4.y; oc[2][2]+=a.z*x4.z; oc[2][3]+=a.z*x4.w;
                oc[3][0]+=a.w*x4.x; oc[3][1]+=a.w*x4.y; oc[3][2]+=a.w*x4.z; oc[3][3]+=a.w*x4.w;
            }
#pragma unroll
            for (int i = 0; i < 4; ++i)
#pragma unroll
                for (int j = 0; j < 4; ++j) {
                    int o = oy4 + i, l = l0 + ox4 + j;
                    out[(size_t)(n*NC_ + o)*L_ + l] = oc[i][j] + cob[o];
                }
        }
    }
}

__global__ void __launch_bounds__(256, 2) layers_kernel(
        const float* __restrict__ convb, const float* __restrict__ qb,
        const float* __restrict__ kb,   const float* __restrict__ vb,
        const float* __restrict__ f1b,  const float* __restrict__ f2b,
        const float* __restrict__ cow,  const float* __restrict__ cob,
        float* __restrict__ out) {
    extern __shared__ char dsm[];
    const int bidx = blockIdx.x;
    for (int layer = 0; layer < NL_; ++layer) {
        const int dil = 1 << layer;
        phaseA(dsm, bidx, layer, dil, convb, qb, kb, vb);
        gbar();
        phaseB(dsm, bidx, dil);
        gbar();
        phaseC(dsm, bidx, layer, f1b, f2b, cow, cob, out, layer == NL_ - 1);
        if (layer < NL_ - 1) gbar();
    }
}

// ---------------- host side ----------------
extern "C" void kernel_launch(void* const* d_in, const int* in_sizes, int n_in,
                              void* d_out, int out_size) {
    (void)in_sizes; (void)n_in; (void)out_size;
    const float* x     = (const float*)d_in[0];
    const int*   t     = (const int*)  d_in[1];
    const float* event = (const float*)d_in[2];
    const float* tw1   = (const float*)d_in[3];
    const float* tb1   = (const float*)d_in[4];
    const float* tw2   = (const float*)d_in[5];
    const float* tb2   = (const float*)d_in[6];
    const float* tpw   = (const float*)d_in[7];
    const float* tpb   = (const float*)d_in[8];
    const float* ciw   = (const float*)d_in[9];
    const float* cib   = (const float*)d_in[10];
    const float* cow   = (const float*)d_in[11];
    const float* cob   = (const float*)d_in[12];
    const float* lcw   = (const float*)d_in[13];
    const float* lcb   = (const float*)d_in[14];
    const float* qw    = (const float*)d_in[15];
    const float* qb    = (const float*)d_in[16];
    const float* kw    = (const float*)d_in[17];
    const float* kb    = (const float*)d_in[18];
    const float* vw    = (const float*)d_in[19];
    const float* vb    = (const float*)d_in[20];
    const float* f1w   = (const float*)d_in[21];
    const float* f1b   = (const float*)d_in[22];
    const float* f2w   = (const float*)d_in[23];
    const float* f2b   = (const float*)d_in[24];

    static cudaStream_t s2 = nullptr;
    static cudaEvent_t ev_fork = nullptr, ev_join = nullptr;
    if (!s2) {
        cudaStreamCreateWithFlags(&s2, cudaStreamNonBlocking);
        cudaEventCreateWithFlags(&ev_fork, cudaEventDisableTiming);
        cudaEventCreateWithFlags(&ev_join, cudaEventDisableTiming);
        cudaFuncSetAttribute(layers_kernel, cudaFuncAttributeMaxDynamicSharedMemorySize, LA_SMEM);
        cudaFuncSetAttribute(gemm_fp16_kernel, cudaFuncAttributeMaxDynamicSharedMemorySize, GM_SMEM);
    }

    // fork: side chain runs temb/pack_aw/conv_in concurrently with xt+GEMM
    cudaEventRecord(ev_fork, 0);
    cudaStreamWaitEvent(s2, ev_fork, 0);
    pack_aw_kernel<<<(NL_*8*64*64)/256, 256, 0, s2>>>(lcw, qw, kw, vw, f1w, f2w);
    temb1_kernel<<<dim3(64, B_), 256, 0, s2>>>(t, tw1, tb1);
    temb2_kernel<<<dim3(64, B_), 256, 0, s2>>>(tw2, tb2);
    tembp_kernel<<<dim3(8, B_), 256, 0, s2>>>(tpw, tpb);
    conv_in_kernel<<<dim3(L_/64, B_), 256, 0, s2>>>(event, ciw, cib);
    cudaEventRecord(ev_join, s2);

    // main chain: weight/input packing then the cross GEMM
    pack_wp_kernel<<<(M_*CR_)/256, 256>>>(qw, kw);
    xt_kernel<<<dim3(L_/32, CR_/32, B_), 256>>>(x);
    gemm_fp16_kernel<<<dim3(M_/GM_BM, NCOL_/GM_BN), 256, GM_SMEM>>>();

    cudaStreamWaitEvent(0, ev_join, 0);
    layers_kernel<<<NBLK, 256, LA_SMEM>>>(lcb, qb, kb, vb, f1b, f2b, cow, cob, (float*)d_out);
}